// round 8
// baseline (speedup 1.0000x reference)
#include <cuda_runtime.h>
#include <cuda_fp16.h>
#include <mma.h>
#include <math.h>

using namespace nvcuda;

#define N_NODES 100000
#define N_PAD   100096
#define N_EDGES 1600000
#define CHN 128
#define OUTCH 64
#define SCAN_T 512
#define SCAN_NB ((N_NODES + SCAN_T - 1) / SCAN_T)   // 196

// ---------------- device scratch ------------------------------------------
__device__ int    g_is64;
__device__ int    g_cnt[N_NODES];
__device__ int    g_row[N_NODES + 1];
__device__ int    g_cur[N_NODES];
__device__ float  g_dis[N_NODES];
__device__ int    g_csr[N_EDGES];
__device__ int    g_bsum[SCAN_NB];
__device__ int    g_boff[SCAN_NB];
__device__ __half g_hs[N_PAD * CHN];
__device__ float  g_x1[N_PAD * CHN];
__device__ float  g_x2[N_PAD * CHN];

// ---------------- edge dtype sniff ----------------------------------------
__global__ void k_sniff(const void* __restrict__ edges) {
    __shared__ int cnt;
    if (threadIdx.x == 0) cnt = 0;
    __syncthreads();
    const int* p = (const int*)edges;
    int z = (p[2 * threadIdx.x + 1] == 0) ? 1 : 0;
    unsigned b = __ballot_sync(0xffffffff, z);
    if ((threadIdx.x & 31) == 0) atomicAdd(&cnt, __popc(b));
    __syncthreads();
    if (threadIdx.x == 0) g_is64 = (cnt > 512) ? 1 : 0;
}

__global__ void k_hist(const void* __restrict__ edges) {
    int base = (blockIdx.x * blockDim.x + threadIdx.x) * 4;
    int is64 = g_is64;
#pragma unroll
    for (int u = 0; u < 4; u++) {
        int i = base + u;
        if (i >= N_EDGES) break;
        int d;
        if (is64) d = (int)((const long long*)edges)[N_EDGES + i];
        else      d = ((const int*)edges)[N_EDGES + i];
        atomicAdd(&g_cnt[d], 1);
    }
}

// ---------------- 3-phase parallel scan ------------------------------------
__global__ void k_scan1() {
    __shared__ int s[SCAN_T];
    int i = blockIdx.x * SCAN_T + threadIdx.x;
    int v = (i < N_NODES) ? g_cnt[i] : 0;
    s[threadIdx.x] = v;
    __syncthreads();
    for (int off = SCAN_T / 2; off > 0; off >>= 1) {
        if (threadIdx.x < off) s[threadIdx.x] += s[threadIdx.x + off];
        __syncthreads();
    }
    if (threadIdx.x == 0) g_bsum[blockIdx.x] = s[0];
}

__global__ void k_scan2() {
    __shared__ int s[256];
    int t = threadIdx.x;
    int v = (t < SCAN_NB) ? g_bsum[t] : 0;
    s[t] = v;
    __syncthreads();
    for (int off = 1; off < 256; off <<= 1) {
        int u = (t >= off) ? s[t - off] : 0;
        __syncthreads();
        s[t] += u;
        __syncthreads();
    }
    if (t < SCAN_NB) g_boff[t] = s[t] - v;
}

__global__ void k_scan3() {
    __shared__ int s[SCAN_T];
    int t = threadIdx.x;
    int i = blockIdx.x * SCAN_T + t;
    int c = (i < N_NODES) ? g_cnt[i] : 0;
    s[t] = c;
    __syncthreads();
    for (int off = 1; off < SCAN_T; off <<= 1) {
        int u = (t >= off) ? s[t - off] : 0;
        __syncthreads();
        s[t] += u;
        __syncthreads();
    }
    if (i < N_NODES) {
        int excl = g_boff[blockIdx.x] + s[t] - c;
        g_row[i] = excl;
        g_cur[i] = excl;
        g_dis[i] = rsqrtf((float)(c + 1));
        if (i == N_NODES - 1) g_row[N_NODES] = excl + c;
    }
}

__global__ void k_fill(const void* __restrict__ edges) {
    int base = (blockIdx.x * blockDim.x + threadIdx.x) * 4;
    int is64 = g_is64;
#pragma unroll
    for (int u = 0; u < 4; u++) {
        int i = base + u;
        if (i >= N_EDGES) break;
        int sN, dN;
        if (is64) {
            const long long* p = (const long long*)edges;
            sN = (int)p[i]; dN = (int)p[N_EDGES + i];
        } else {
            const int* p = (const int*)edges;
            sN = p[i]; dN = p[N_EDGES + i];
        }
        int idx = atomicAdd(&g_cur[dN], 1);
        g_csr[idx] = sN;
    }
}

// ---------------- tf32 GEMM: A[M,128] @ B[128,128] -> half, dis-scaled ----
#define AS_FLOATS (192 * 36)
#define BS_FLOATS (32 * 136)

__global__ __launch_bounds__(256) void gemm_tf32(
    const float* __restrict__ A, const float* __restrict__ B,
    __half* __restrict__ out, const float* __restrict__ dis, int M)
{
    __shared__ float pool[AS_FLOATS + BS_FLOATS];
    float (*As)[36]  = (float(*)[36])pool;
    float (*Bs)[136] = (float(*)[136])(pool + AS_FLOATS);
    float (*stage)[16][20] = (float(*)[16][20])pool;   // aliases As (dead)

    int tid = threadIdx.x;
    int wid = tid >> 5;
    int lane = tid & 31;
    int wm = wid & 3;
    int wn = wid >> 2;
    int bm = blockIdx.x * 192;

    wmma::fragment<wmma::accumulator, 16, 16, 8, float> acc[3][4];
#pragma unroll
    for (int i = 0; i < 3; i++)
#pragma unroll
        for (int j = 0; j < 4; j++) wmma::fill_fragment(acc[i][j], 0.f);

    for (int k0 = 0; k0 < 128; k0 += 32) {
#pragma unroll
        for (int h = 0; h < 6; h++) {
            int i4 = tid + h * 256;
            int r = i4 >> 3, c = (i4 & 7) * 4;
            float4 v = make_float4(0.f, 0.f, 0.f, 0.f);
            if (bm + r < M) v = *(const float4*)(A + (long)(bm + r) * 128 + k0 + c);
            As[r][c + 0] = wmma::__float_to_tf32(v.x);
            As[r][c + 1] = wmma::__float_to_tf32(v.y);
            As[r][c + 2] = wmma::__float_to_tf32(v.z);
            As[r][c + 3] = wmma::__float_to_tf32(v.w);
        }
#pragma unroll
        for (int h = 0; h < 4; h++) {
            int i4 = tid + h * 256;
            int r = i4 >> 5, c = (i4 & 31) * 4;
            float4 v = *(const float4*)(B + (long)(k0 + r) * 128 + c);
            Bs[r][c + 0] = wmma::__float_to_tf32(v.x);
            Bs[r][c + 1] = wmma::__float_to_tf32(v.y);
            Bs[r][c + 2] = wmma::__float_to_tf32(v.z);
            Bs[r][c + 3] = wmma::__float_to_tf32(v.w);
        }
        __syncthreads();
#pragma unroll
        for (int kk = 0; kk < 4; kk++) {
            wmma::fragment<wmma::matrix_a, 16, 16, 8, wmma::precision::tf32, wmma::row_major> af[3];
            wmma::fragment<wmma::matrix_b, 16, 16, 8, wmma::precision::tf32, wmma::row_major> bf[4];
#pragma unroll
            for (int i = 0; i < 3; i++)
                wmma::load_matrix_sync(af[i], &As[wm * 48 + i * 16][kk * 8], 36);
#pragma unroll
            for (int j = 0; j < 4; j++)
                wmma::load_matrix_sync(bf[j], &Bs[kk * 8][wn * 64 + j * 16], 136);
#pragma unroll
            for (int i = 0; i < 3; i++)
#pragma unroll
                for (int j = 0; j < 4; j++)
                    wmma::mma_sync(acc[i][j], af[i], bf[j], acc[i][j]);
        }
        __syncthreads();
    }
#pragma unroll
    for (int i = 0; i < 3; i++)
#pragma unroll
        for (int j = 0; j < 4; j++) {
            wmma::store_matrix_sync(&stage[wid][0][0], acc[i][j], 20, wmma::mem_row_major);
            __syncwarp();
            int r = bm + wm * 48 + i * 16 + (lane >> 1);
            float dsc = (r < M) ? dis[r] : 0.f;
            const float* srow = &stage[wid][lane >> 1][(lane & 1) * 8];
            __half2 h0 = __float22half2_rn(make_float2(srow[0] * dsc, srow[1] * dsc));
            __half2 h1 = __float22half2_rn(make_float2(srow[2] * dsc, srow[3] * dsc));
            __half2 h2 = __float22half2_rn(make_float2(srow[4] * dsc, srow[5] * dsc));
            __half2 h3 = __float22half2_rn(make_float2(srow[6] * dsc, srow[7] * dsc));
            uint4 pack;
            pack.x = *(unsigned*)&h0;
            pack.y = *(unsigned*)&h1;
            pack.z = *(unsigned*)&h2;
            pack.w = *(unsigned*)&h3;
            *(uint4*)(out + (long)r * 128 + wn * 64 + j * 16 + (lane & 1) * 8) = pack;
            __syncwarp();
        }
}

// ---------------- tf32 output GEMM: (x1+x2)[M,128] @ Wo[128,64] + bo ------
__global__ __launch_bounds__(256) void gemm_out_tf32(
    const float* __restrict__ A1, const float* __restrict__ A2,
    const float* __restrict__ B, const float* __restrict__ bias,
    float* __restrict__ out, int M)
{
    __shared__ float As[128][36];
    __shared__ float Bs[32][72];
    __shared__ float Bt[16][72];
    int tid = threadIdx.x;
    int wid = tid >> 5;
    int bm = blockIdx.x * 128;

    for (int i = tid; i < 16 * 64; i += 256) Bt[i >> 6][i & 63] = bias[i & 63];
    __syncthreads();

    wmma::fragment<wmma::accumulator, 16, 16, 8, float> acc[4];
#pragma unroll
    for (int j = 0; j < 4; j++)
        wmma::load_matrix_sync(acc[j], &Bt[0][j * 16], 72, wmma::mem_row_major);

    for (int k0 = 0; k0 < 128; k0 += 32) {
#pragma unroll
        for (int h = 0; h < 4; h++) {
            int i4 = tid + h * 256;
            int r = i4 >> 3, c = (i4 & 7) * 4;
            float4 v = make_float4(0.f, 0.f, 0.f, 0.f);
            if (bm + r < M) {
                float4 u = *(const float4*)(A1 + (long)(bm + r) * 128 + k0 + c);
                float4 w = *(const float4*)(A2 + (long)(bm + r) * 128 + k0 + c);
                v.x = u.x + w.x; v.y = u.y + w.y; v.z = u.z + w.z; v.w = u.w + w.w;
            }
            As[r][c + 0] = wmma::__float_to_tf32(v.x);
            As[r][c + 1] = wmma::__float_to_tf32(v.y);
            As[r][c + 2] = wmma::__float_to_tf32(v.z);
            As[r][c + 3] = wmma::__float_to_tf32(v.w);
        }
        {
            int r = tid >> 4, c = (tid & 15) * 4;
            float4 v = *(const float4*)(B + (long)(k0 + r) * 64 + c);
            Bs[r][c + 0] = wmma::__float_to_tf32(v.x);
            Bs[r][c + 1] = wmma::__float_to_tf32(v.y);
            Bs[r][c + 2] = wmma::__float_to_tf32(v.z);
            Bs[r][c + 3] = wmma::__float_to_tf32(v.w);
            r = (tid + 256) >> 4; c = ((tid + 256) & 15) * 4;
            v = *(const float4*)(B + (long)(k0 + r) * 64 + c);
            Bs[r][c + 0] = wmma::__float_to_tf32(v.x);
            Bs[r][c + 1] = wmma::__float_to_tf32(v.y);
            Bs[r][c + 2] = wmma::__float_to_tf32(v.z);
            Bs[r][c + 3] = wmma::__float_to_tf32(v.w);
        }
        __syncthreads();
#pragma unroll
        for (int kk = 0; kk < 4; kk++) {
            wmma::fragment<wmma::matrix_a, 16, 16, 8, wmma::precision::tf32, wmma::row_major> af;
            wmma::fragment<wmma::matrix_b, 16, 16, 8, wmma::precision::tf32, wmma::row_major> bf[4];
            wmma::load_matrix_sync(af, &As[wid * 16][kk * 8], 36);
#pragma unroll
            for (int j = 0; j < 4; j++)
                wmma::load_matrix_sync(bf[j], &Bs[kk * 8][j * 16], 72);
#pragma unroll
            for (int j = 0; j < 4; j++)
                wmma::mma_sync(acc[j], af, bf[j], acc[j]);
        }
        __syncthreads();
    }
    int r = bm + wid * 16;
    if (r + 16 <= M) {
#pragma unroll
        for (int j = 0; j < 4; j++)
            wmma::store_matrix_sync(out + (long)r * 64 + j * 16,
                                    acc[j], 64, wmma::mem_row_major);
    }
}

// ---------------- aggregation: 2 warps/node (64 ch each), prefetched ------
__global__ __launch_bounds__(256) void aggregate_s(
    const __half* __restrict__ hs, const float* __restrict__ bias,
    float* __restrict__ xo)
{
    int gwarp = (blockIdx.x * blockDim.x + threadIdx.x) >> 5;
    int node = gwarp >> 1;
    int lane = threadIdx.x & 31;
    if (node >= N_NODES) return;
    int ch = (gwarp & 1) * 64 + lane * 2;          // 2 channels per lane
    const __half* hp = hs + ch;

    int beg = g_row[node];
    int end = g_row[node + 1];

    float2 acc;
    {
        unsigned raw = *(const unsigned*)(hp + (long)node * 128);
        acc = __half22float2(*(const __half2*)&raw);   // self, pre-scaled
    }

    int e = beg;
    int n8 = (end - beg) >> 3;
    if (n8 > 0) {
        // prefetch first index batch
        int idx[8];
#pragma unroll
        for (int u = 0; u < 8; u++) idx[u] = g_csr[e + u];
        for (int b = 1; b <= n8; b++) {
            int nxt[8];
            if (b < n8) {
#pragma unroll
                for (int u = 0; u < 8; u++) nxt[u] = g_csr[e + 8 + u];
            }
            unsigned raw[8];
#pragma unroll
            for (int u = 0; u < 8; u++)
                raw[u] = *(const unsigned*)(hp + (long)idx[u] * 128);
#pragma unroll
            for (int u = 0; u < 8; u++) {
                float2 v = __half22float2(*(const __half2*)&raw[u]);
                acc.x += v.x; acc.y += v.y;
            }
#pragma unroll
            for (int u = 0; u < 8; u++) idx[u] = nxt[u];
            e += 8;
        }
    }
    for (; e < end; e++) {
        unsigned raw = *(const unsigned*)(hp + (long)g_csr[e] * 128);
        float2 v = __half22float2(*(const __half2*)&raw);
        acc.x += v.x; acc.y += v.y;
    }

    float dd = g_dis[node];
    float2 b2 = *(const float2*)(bias + ch);
    float2 o;
    o.x = fmaxf(acc.x * dd + b2.x, 0.f);
    o.y = fmaxf(acc.y * dd + b2.y, 0.f);
    *(float2*)(xo + (long)node * 128 + ch) = o;
}

// ---------------- launch ---------------------------------------------------
extern "C" void kernel_launch(void* const* d_in, const int* in_sizes, int n_in,
                              void* d_out, int out_size)
{
    const float* x  = (const float*)d_in[0];
    const void*  ei = d_in[1];
    const float* W1 = (const float*)d_in[2];
    const float* b1 = (const float*)d_in[3];
    const float* W2 = (const float*)d_in[4];
    const float* b2 = (const float*)d_in[5];
    const float* Wo = (const float*)d_in[6];
    const float* bo = (const float*)d_in[7];
    float* out = (float*)d_out;

    __half* hs;
    float *x1, *x2, *dis;
    int* cnt;
    cudaGetSymbolAddress((void**)&hs,  g_hs);
    cudaGetSymbolAddress((void**)&x1,  g_x1);
    cudaGetSymbolAddress((void**)&x2,  g_x2);
    cudaGetSymbolAddress((void**)&dis, g_dis);
    cudaGetSymbolAddress((void**)&cnt, g_cnt);

    const int M = N_NODES;
    int gB  = (M + 191) / 192;
    int gBo = (M + 127) / 128;
    int gE4 = (N_EDGES + 1023) / 1024;
    int gAg = ((M * 2) * 32 + 255) / 256;     // 2 warps per node

    cudaMemsetAsync(cnt, 0, N_NODES * sizeof(int));
    k_sniff<<<1, 1024>>>(ei);
    k_hist<<<gE4, 256>>>(ei);
    k_scan1<<<SCAN_NB, SCAN_T>>>();
    k_scan2<<<1, 256>>>();
    k_scan3<<<SCAN_NB, SCAN_T>>>();
    k_fill<<<gE4, 256>>>(ei);

    gemm_tf32<<<gB, 256>>>(x, W1, hs, dis, M);
    aggregate_s<<<gAg, 256>>>(hs, b1, x1);
    gemm_tf32<<<gB, 256>>>(x1, W2, hs, dis, M);
    aggregate_s<<<gAg, 256>>>(hs, b2, x2);
    gemm_out_tf32<<<gBo, 256>>>(x1, x2, Wo, bo, out, M);
}

// round 10
// speedup vs baseline: 1.1568x; 1.1568x over previous
#include <cuda_runtime.h>
#include <cuda_fp16.h>
#include <mma.h>
#include <math.h>

using namespace nvcuda;

#define N_NODES 100000
#define N_PAD   100096
#define N_EDGES 1600000
#define CHN 128
#define OUTCH 64
#define SCAN_T 512
#define SCAN_NB ((N_NODES + SCAN_T - 1) / SCAN_T)   // 196

// ---------------- device scratch ------------------------------------------
__device__ int    g_is64;
__device__ int    g_cnt[N_NODES];
__device__ int    g_row[N_NODES + 1];
__device__ int    g_cur[N_NODES];
__device__ float  g_dis[N_NODES];
__device__ int    g_csr[N_EDGES];
__device__ int    g_bsum[SCAN_NB];
__device__ int    g_boff[SCAN_NB];
__device__ __half g_hs[N_PAD * CHN];
__device__ float  g_x1[N_PAD * CHN];
__device__ float  g_x2[N_PAD * CHN];

// ---------------- cp.async helpers ----------------------------------------
__device__ __forceinline__ void cp16(void* smem, const void* g, bool pred) {
    unsigned s = (unsigned)__cvta_generic_to_shared(smem);
    int sz = pred ? 16 : 0;
    asm volatile("cp.async.cg.shared.global [%0], [%1], 16, %2;\n"
                 :: "r"(s), "l"(g), "r"(sz));
}
__device__ __forceinline__ void cp_commit() {
    asm volatile("cp.async.commit_group;\n");
}
template <int N>
__device__ __forceinline__ void cp_wait() {
    asm volatile("cp.async.wait_group %0;\n" :: "n"(N));
}

template <typename Frag>
__device__ __forceinline__ void frag_rn(Frag& f) {
#pragma unroll
    for (int i = 0; i < f.num_elements; i++) f.x[i] = wmma::__float_to_tf32(f.x[i]);
}

// ---------------- edge dtype sniff ----------------------------------------
__global__ void k_sniff(const void* __restrict__ edges) {
    __shared__ int cnt;
    if (threadIdx.x == 0) cnt = 0;
    __syncthreads();
    const int* p = (const int*)edges;
    int z = (p[2 * threadIdx.x + 1] == 0) ? 1 : 0;
    unsigned b = __ballot_sync(0xffffffff, z);
    if ((threadIdx.x & 31) == 0) atomicAdd(&cnt, __popc(b));
    __syncthreads();
    if (threadIdx.x == 0) g_is64 = (cnt > 512) ? 1 : 0;
}

__global__ void k_hist(const void* __restrict__ edges) {
    int base = (blockIdx.x * blockDim.x + threadIdx.x) * 8;
    int is64 = g_is64;
#pragma unroll
    for (int u = 0; u < 8; u++) {
        int i = base + u;
        if (i >= N_EDGES) break;
        int d;
        if (is64) d = (int)((const long long*)edges)[N_EDGES + i];
        else      d = ((const int*)edges)[N_EDGES + i];
        atomicAdd(&g_cnt[d], 1);
    }
}

// ---------------- 3-phase parallel scan ------------------------------------
__global__ void k_scan1() {
    __shared__ int s[SCAN_T];
    int i = blockIdx.x * SCAN_T + threadIdx.x;
    int v = (i < N_NODES) ? g_cnt[i] : 0;
    s[threadIdx.x] = v;
    __syncthreads();
    for (int off = SCAN_T / 2; off > 0; off >>= 1) {
        if (threadIdx.x < off) s[threadIdx.x] += s[threadIdx.x + off];
        __syncthreads();
    }
    if (threadIdx.x == 0) g_bsum[blockIdx.x] = s[0];
}

__global__ void k_scan2() {
    __shared__ int s[256];
    int t = threadIdx.x;
    int v = (t < SCAN_NB) ? g_bsum[t] : 0;
    s[t] = v;
    __syncthreads();
    for (int off = 1; off < 256; off <<= 1) {
        int u = (t >= off) ? s[t - off] : 0;
        __syncthreads();
        s[t] += u;
        __syncthreads();
    }
    if (t < SCAN_NB) g_boff[t] = s[t] - v;
}

__global__ void k_scan3() {
    __shared__ int s[SCAN_T];
    int t = threadIdx.x;
    int i = blockIdx.x * SCAN_T + t;
    int c = (i < N_NODES) ? g_cnt[i] : 0;
    s[t] = c;
    __syncthreads();
    for (int off = 1; off < SCAN_T; off <<= 1) {
        int u = (t >= off) ? s[t - off] : 0;
        __syncthreads();
        s[t] += u;
        __syncthreads();
    }
    if (i < N_NODES) {
        int excl = g_boff[blockIdx.x] + s[t] - c;
        g_row[i] = excl;
        g_cur[i] = excl;
        g_dis[i] = rsqrtf((float)(c + 1));
        if (i == N_NODES - 1) g_row[N_NODES] = excl + c;
    }
}

__global__ void k_fill(const void* __restrict__ edges) {
    int base = (blockIdx.x * blockDim.x + threadIdx.x) * 8;
    int is64 = g_is64;
#pragma unroll
    for (int u = 0; u < 8; u++) {
        int i = base + u;
        if (i >= N_EDGES) break;
        int sN, dN;
        if (is64) {
            const long long* p = (const long long*)edges;
            sN = (int)p[i]; dN = (int)p[N_EDGES + i];
        } else {
            const int* p = (const int*)edges;
            sN = p[i]; dN = p[N_EDGES + i];
        }
        int idx = atomicAdd(&g_cur[dN], 1);
        g_csr[idx] = sN;
    }
}

// ---------------- tf32 GEMM, cp.async double-buffered, RN in fragments ----
#define AS_FLOATS (192 * 36)
#define BS_FLOATS (32 * 136)
#define STAGE_FLOATS (AS_FLOATS + BS_FLOATS)
#define GEMM_SMEM_BYTES (2 * STAGE_FLOATS * 4)

__global__ __launch_bounds__(256) void gemm_tf32(
    const float* __restrict__ A, const float* __restrict__ B,
    __half* __restrict__ out, const float* __restrict__ dis, int M)
{
    extern __shared__ float pool[];
    int tid = threadIdx.x;
    int wid = tid >> 5;
    int lane = tid & 31;
    int wm = wid & 3;
    int wn = wid >> 2;
    int bm = blockIdx.x * 192;

    wmma::fragment<wmma::accumulator, 16, 16, 8, float> acc[3][4];
#pragma unroll
    for (int i = 0; i < 3; i++)
#pragma unroll
        for (int j = 0; j < 4; j++) wmma::fill_fragment(acc[i][j], 0.f);

    int ar = tid >> 3, ac = (tid & 7) * 4;
    int br = tid >> 5, bc = (tid & 31) * 4;

    auto load_stage = [&](int k0, int s) {
        float* As = pool + s * STAGE_FLOATS;
        float* Bs = As + AS_FLOATS;
#pragma unroll
        for (int h = 0; h < 6; h++) {
            int r = ar + h * 32;
            bool ok = (bm + r < M);
            cp16(&As[r * 36 + ac],
                 A + (long)(bm + r) * 128 + k0 + ac, ok);
        }
#pragma unroll
        for (int h = 0; h < 4; h++) {
            int r = br + h * 8;
            cp16(&Bs[r * 136 + bc],
                 B + (long)(k0 + r) * 128 + bc, true);
        }
        cp_commit();
    };

    load_stage(0, 0);
#pragma unroll
    for (int ck = 0; ck < 4; ck++) {
        if (ck < 3) load_stage((ck + 1) * 32, (ck + 1) & 1);
        if (ck < 3) cp_wait<1>(); else cp_wait<0>();
        __syncthreads();
        float* As = pool + (ck & 1) * STAGE_FLOATS;
        float* Bs = As + AS_FLOATS;
#pragma unroll
        for (int kk = 0; kk < 4; kk++) {
            wmma::fragment<wmma::matrix_a, 16, 16, 8, wmma::precision::tf32, wmma::row_major> af[3];
            wmma::fragment<wmma::matrix_b, 16, 16, 8, wmma::precision::tf32, wmma::row_major> bf[4];
#pragma unroll
            for (int i = 0; i < 3; i++) {
                wmma::load_matrix_sync(af[i], &As[(wm * 48 + i * 16) * 36 + kk * 8], 36);
                frag_rn(af[i]);
            }
#pragma unroll
            for (int j = 0; j < 4; j++) {
                wmma::load_matrix_sync(bf[j], &Bs[(kk * 8) * 136 + wn * 64 + j * 16], 136);
                frag_rn(bf[j]);
            }
#pragma unroll
            for (int i = 0; i < 3; i++)
#pragma unroll
                for (int j = 0; j < 4; j++)
                    wmma::mma_sync(acc[i][j], af[i], bf[j], acc[i][j]);
        }
        __syncthreads();
    }

    float (*stage)[16][20] = (float(*)[16][20])pool;
#pragma unroll
    for (int i = 0; i < 3; i++)
#pragma unroll
        for (int j = 0; j < 4; j++) {
            wmma::store_matrix_sync(&stage[wid][0][0], acc[i][j], 20, wmma::mem_row_major);
            __syncwarp();
            int r = bm + wm * 48 + i * 16 + (lane >> 1);
            float dsc = (r < M) ? dis[r] : 0.f;
            const float* srow = &stage[wid][lane >> 1][(lane & 1) * 8];
            __half2 h0 = __float22half2_rn(make_float2(srow[0] * dsc, srow[1] * dsc));
            __half2 h1 = __float22half2_rn(make_float2(srow[2] * dsc, srow[3] * dsc));
            __half2 h2 = __float22half2_rn(make_float2(srow[4] * dsc, srow[5] * dsc));
            __half2 h3 = __float22half2_rn(make_float2(srow[6] * dsc, srow[7] * dsc));
            uint4 pack;
            pack.x = *(unsigned*)&h0;
            pack.y = *(unsigned*)&h1;
            pack.z = *(unsigned*)&h2;
            pack.w = *(unsigned*)&h3;
            *(uint4*)(out + (long)r * 128 + wn * 64 + j * 16 + (lane & 1) * 8) = pack;
            __syncwarp();
        }
}

// ---------------- tf32 output GEMM: (x1+x2)[M,128] @ Wo[128,64] + bo ------
__global__ __launch_bounds__(256) void gemm_out_tf32(
    const float* __restrict__ A1, const float* __restrict__ A2,
    const float* __restrict__ B, const float* __restrict__ bias,
    float* __restrict__ out, int M)
{
    __shared__ float As[128][36];
    __shared__ float Bs[32][72];
    __shared__ float Bt[16][72];
    int tid = threadIdx.x;
    int wid = tid >> 5;
    int bm = blockIdx.x * 128;

    for (int i = tid; i < 16 * 64; i += 256) Bt[i >> 6][i & 63] = bias[i & 63];
    __syncthreads();

    wmma::fragment<wmma::accumulator, 16, 16, 8, float> acc[4];
#pragma unroll
    for (int j = 0; j < 4; j++)
        wmma::load_matrix_sync(acc[j], &Bt[0][j * 16], 72, wmma::mem_row_major);

    for (int k0 = 0; k0 < 128; k0 += 32) {
#pragma unroll
        for (int h = 0; h < 4; h++) {
            int i4 = tid + h * 256;
            int r = i4 >> 3, c = (i4 & 7) * 4;
            float4 v = make_float4(0.f, 0.f, 0.f, 0.f);
            if (bm + r < M) {
                float4 u = *(const float4*)(A1 + (long)(bm + r) * 128 + k0 + c);
                float4 w = *(const float4*)(A2 + (long)(bm + r) * 128 + k0 + c);
                v.x = u.x + w.x; v.y = u.y + w.y; v.z = u.z + w.z; v.w = u.w + w.w;
            }
            As[r][c + 0] = wmma::__float_to_tf32(v.x);
            As[r][c + 1] = wmma::__float_to_tf32(v.y);
            As[r][c + 2] = wmma::__float_to_tf32(v.z);
            As[r][c + 3] = wmma::__float_to_tf32(v.w);
        }
        {
            int r = tid >> 4, c = (tid & 15) * 4;
            float4 v = *(const float4*)(B + (long)(k0 + r) * 64 + c);
            Bs[r][c + 0] = wmma::__float_to_tf32(v.x);
            Bs[r][c + 1] = wmma::__float_to_tf32(v.y);
            Bs[r][c + 2] = wmma::__float_to_tf32(v.z);
            Bs[r][c + 3] = wmma::__float_to_tf32(v.w);
            r = (tid + 256) >> 4; c = ((tid + 256) & 15) * 4;
            v = *(const float4*)(B + (long)(k0 + r) * 64 + c);
            Bs[r][c + 0] = wmma::__float_to_tf32(v.x);
            Bs[r][c + 1] = wmma::__float_to_tf32(v.y);
            Bs[r][c + 2] = wmma::__float_to_tf32(v.z);
            Bs[r][c + 3] = wmma::__float_to_tf32(v.w);
        }
        __syncthreads();
#pragma unroll
        for (int kk = 0; kk < 4; kk++) {
            wmma::fragment<wmma::matrix_a, 16, 16, 8, wmma::precision::tf32, wmma::row_major> af;
            wmma::fragment<wmma::matrix_b, 16, 16, 8, wmma::precision::tf32, wmma::row_major> bf[4];
            wmma::load_matrix_sync(af, &As[wid * 16][kk * 8], 36);
#pragma unroll
            for (int j = 0; j < 4; j++)
                wmma::load_matrix_sync(bf[j], &Bs[kk * 8][j * 16], 72);
#pragma unroll
            for (int j = 0; j < 4; j++)
                wmma::mma_sync(acc[j], af, bf[j], acc[j]);
        }
        __syncthreads();
    }
    int r = bm + wid * 16;
    if (r + 16 <= M) {
#pragma unroll
        for (int j = 0; j < 4; j++)
            wmma::store_matrix_sync(out + (long)r * 64 + j * 16,
                                    acc[j], 64, wmma::mem_row_major);
    }
}

// ---------------- aggregation (R7 version): warp/node, 8-wide, plain sum --
__device__ __forceinline__ float4 gather_h(const __half* hs, int s, int lane) {
    uint2 raw = *(const uint2*)(hs + (long)s * 128 + lane * 4);
    float2 a = __half22float2(*(__half2*)&raw.x);
    float2 b = __half22float2(*(__half2*)&raw.y);
    return make_float4(a.x, a.y, b.x, b.y);
}

__global__ __launch_bounds__(256) void aggregate_s(
    const __half* __restrict__ hs, const float* __restrict__ bias,
    float* __restrict__ xo)
{
    int gw = (blockIdx.x * blockDim.x + threadIdx.x) >> 5;
    int lane = threadIdx.x & 31;
    if (gw >= N_NODES) return;
    int beg = g_row[gw];
    int end = g_row[gw + 1];
    float4 acc = gather_h(hs, gw, lane);   // self term, pre-scaled
    int e = beg;
    for (; e + 8 <= end; e += 8) {
        int s0 = g_csr[e],     s1 = g_csr[e + 1], s2 = g_csr[e + 2], s3 = g_csr[e + 3];
        int s4 = g_csr[e + 4], s5 = g_csr[e + 5], s6 = g_csr[e + 6], s7 = g_csr[e + 7];
        float4 v0 = gather_h(hs, s0, lane);
        float4 v1 = gather_h(hs, s1, lane);
        float4 v2 = gather_h(hs, s2, lane);
        float4 v3 = gather_h(hs, s3, lane);
        float4 v4 = gather_h(hs, s4, lane);
        float4 v5 = gather_h(hs, s5, lane);
        float4 v6 = gather_h(hs, s6, lane);
        float4 v7 = gather_h(hs, s7, lane);
        acc.x += (v0.x + v1.x) + (v2.x + v3.x) + (v4.x + v5.x) + (v6.x + v7.x);
        acc.y += (v0.y + v1.y) + (v2.y + v3.y) + (v4.y + v5.y) + (v6.y + v7.y);
        acc.z += (v0.z + v1.z) + (v2.z + v3.z) + (v4.z + v5.z) + (v6.z + v7.z);
        acc.w += (v0.w + v1.w) + (v2.w + v3.w) + (v4.w + v5.w) + (v6.w + v7.w);
    }
    for (; e < end; e++) {
        float4 v = gather_h(hs, g_csr[e], lane);
        acc.x += v.x; acc.y += v.y; acc.z += v.z; acc.w += v.w;
    }
    float dd = g_dis[gw];
    float4 b = *(const float4*)(bias + lane * 4);
    float4 o;
    o.x = fmaxf(acc.x * dd + b.x, 0.f);
    o.y = fmaxf(acc.y * dd + b.y, 0.f);
    o.z = fmaxf(acc.z * dd + b.z, 0.f);
    o.w = fmaxf(acc.w * dd + b.w, 0.f);
    *(float4*)(xo + (long)gw * 128 + lane * 4) = o;
}

// ---------------- launch ---------------------------------------------------
extern "C" void kernel_launch(void* const* d_in, const int* in_sizes, int n_in,
                              void* d_out, int out_size)
{
    const float* x  = (const float*)d_in[0];
    const void*  ei = d_in[1];
    const float* W1 = (const float*)d_in[2];
    const float* b1 = (const float*)d_in[3];
    const float* W2 = (const float*)d_in[4];
    const float* b2 = (const float*)d_in[5];
    const float* Wo = (const float*)d_in[6];
    const float* bo = (const float*)d_in[7];
    float* out = (float*)d_out;

    __half* hs;
    float *x1, *x2, *dis;
    int* cnt;
    cudaGetSymbolAddress((void**)&hs,  g_hs);
    cudaGetSymbolAddress((void**)&x1,  g_x1);
    cudaGetSymbolAddress((void**)&x2,  g_x2);
    cudaGetSymbolAddress((void**)&dis, g_dis);
    cudaGetSymbolAddress((void**)&cnt, g_cnt);

    cudaFuncSetAttribute(gemm_tf32,
        cudaFuncAttributeMaxDynamicSharedMemorySize, GEMM_SMEM_BYTES);

    const int M = N_NODES;
    int gB  = (M + 191) / 192;
    int gBo = (M + 127) / 128;
    int gE8 = (N_EDGES + 2047) / 2048;
    int gAg = (M * 32 + 255) / 256;

    cudaMemsetAsync(cnt, 0, N_NODES * sizeof(int));
    k_sniff<<<1, 1024>>>(ei);
    k_hist<<<gE8, 256>>>(ei);
    k_scan1<<<SCAN_NB, SCAN_T>>>();
    k_scan2<<<1, 256>>>();
    k_scan3<<<SCAN_NB, SCAN_T>>>();
    k_fill<<<gE8, 256>>>(ei);

    gemm_tf32<<<gB, 256, GEMM_SMEM_BYTES>>>(x, W1, hs, dis, M);
    aggregate_s<<<gAg, 256>>>(hs, b1, x1);
    gemm_tf32<<<gB, 256, GEMM_SMEM_BYTES>>>(x1, W2, hs, dis, M);
    aggregate_s<<<gAg, 256>>>(hs, b2, x2);
    gemm_out_tf32<<<gBo, 256>>>(x1, x2, Wo, bo, out, M);
}

// round 11
// speedup vs baseline: 1.2115x; 1.0473x over previous
#include <cuda_runtime.h>
#include <cuda_fp16.h>
#include <mma.h>
#include <math.h>

using namespace nvcuda;

#define N_NODES 100000
#define N_PAD   100096
#define N_EDGES 1600000
#define CHN 128
#define OUTCH 64
#define SCAN_T 512
#define SCAN_NB ((N_NODES + SCAN_T - 1) / SCAN_T)   // 196

// ---------------- device scratch ------------------------------------------
__device__ int    g_is64;
__device__ int    g_cnt[N_NODES];
__device__ int    g_row[N_NODES + 1];
__device__ int    g_cur[N_NODES];
__device__ float  g_dis[N_NODES];
__device__ int    g_csr[N_EDGES];
__device__ int    g_bsum[SCAN_NB];
__device__ int    g_boff[SCAN_NB];
__device__ __half g_hs[N_PAD * CHN];
__device__ __half g_x1[N_PAD * CHN];
__device__ __half g_x2[N_PAD * CHN];

// ---------------- init: zero counters + dtype sniff ------------------------
__global__ void k_init(const void* __restrict__ edges) {
    int i = blockIdx.x * blockDim.x + threadIdx.x;
    if (i < N_NODES) g_cnt[i] = 0;
    if (blockIdx.x == 0) {
        __shared__ int cnt;
        if (threadIdx.x == 0) cnt = 0;
        __syncthreads();
        const int* p = (const int*)edges;
        int z = 0;
#pragma unroll
        for (int u = 0; u < 4; u++) {
            int w = (threadIdx.x * 4 + u) * 2 + 1;   // odd words 1..2047
            z += (p[w] == 0);
        }
        unsigned b = __ballot_sync(0xffffffff, z > 0);
        (void)b;
        atomicAdd(&cnt, z);
        __syncthreads();
        if (threadIdx.x == 0) g_is64 = (cnt > 512) ? 1 : 0;
    }
}

__global__ void k_hist(const void* __restrict__ edges) {
    int base = (blockIdx.x * blockDim.x + threadIdx.x) * 8;
    int is64 = g_is64;
#pragma unroll
    for (int u = 0; u < 8; u++) {
        int i = base + u;
        if (i >= N_EDGES) break;
        int d;
        if (is64) d = (int)((const long long*)edges)[N_EDGES + i];
        else      d = ((const int*)edges)[N_EDGES + i];
        atomicAdd(&g_cnt[d], 1);
    }
}

// ---------------- 3-phase parallel scan ------------------------------------
__global__ void k_scan1() {
    __shared__ int s[SCAN_T];
    int i = blockIdx.x * SCAN_T + threadIdx.x;
    int v = (i < N_NODES) ? g_cnt[i] : 0;
    s[threadIdx.x] = v;
    __syncthreads();
    for (int off = SCAN_T / 2; off > 0; off >>= 1) {
        if (threadIdx.x < off) s[threadIdx.x] += s[threadIdx.x + off];
        __syncthreads();
    }
    if (threadIdx.x == 0) g_bsum[blockIdx.x] = s[0];
}

__global__ void k_scan2() {
    __shared__ int s[256];
    int t = threadIdx.x;
    int v = (t < SCAN_NB) ? g_bsum[t] : 0;
    s[t] = v;
    __syncthreads();
    for (int off = 1; off < 256; off <<= 1) {
        int u = (t >= off) ? s[t - off] : 0;
        __syncthreads();
        s[t] += u;
        __syncthreads();
    }
    if (t < SCAN_NB) g_boff[t] = s[t] - v;
}

__global__ void k_scan3() {
    __shared__ int s[SCAN_T];
    int t = threadIdx.x;
    int i = blockIdx.x * SCAN_T + t;
    int c = (i < N_NODES) ? g_cnt[i] : 0;
    s[t] = c;
    __syncthreads();
    for (int off = 1; off < SCAN_T; off <<= 1) {
        int u = (t >= off) ? s[t - off] : 0;
        __syncthreads();
        s[t] += u;
        __syncthreads();
    }
    if (i < N_NODES) {
        int excl = g_boff[blockIdx.x] + s[t] - c;
        g_row[i] = excl;
        g_cur[i] = excl;
        g_dis[i] = rsqrtf((float)(c + 1));
        if (i == N_NODES - 1) g_row[N_NODES] = excl + c;
    }
}

__global__ void k_fill(const void* __restrict__ edges) {
    int base = (blockIdx.x * blockDim.x + threadIdx.x) * 8;
    int is64 = g_is64;
#pragma unroll
    for (int u = 0; u < 8; u++) {
        int i = base + u;
        if (i >= N_EDGES) break;
        int sN, dN;
        if (is64) {
            const long long* p = (const long long*)edges;
            sN = (int)p[i]; dN = (int)p[N_EDGES + i];
        } else {
            const int* p = (const int*)edges;
            sN = p[i]; dN = p[N_EDGES + i];
        }
        int idx = atomicAdd(&g_cur[dN], 1);
        g_csr[idx] = sN;
    }
}

// ---------------- tf32 GEMM (R7 structure): A[M,128] @ B[128,128] ---------
// Templated A dtype (float or __half); converts to tf32 at smem store.
// Epilogue: row-scale by dis[r], emit fp16.
#define AS_FLOATS (192 * 36)
#define BS_FLOATS (32 * 136)

template <typename AT>
__global__ __launch_bounds__(256) void gemm_tf32(
    const AT* __restrict__ A, const float* __restrict__ B,
    __half* __restrict__ out, const float* __restrict__ dis, int M)
{
    __shared__ float pool[AS_FLOATS + BS_FLOATS];   // 45056 B
    float (*As)[36]  = (float(*)[36])pool;
    float (*Bs)[136] = (float(*)[136])(pool + AS_FLOATS);
    float (*stage)[16][20] = (float(*)[16][20])pool;   // aliases As (dead)

    int tid = threadIdx.x;
    int wid = tid >> 5;
    int lane = tid & 31;
    int wm = wid & 3;
    int wn = wid >> 2;
    int bm = blockIdx.x * 192;

    wmma::fragment<wmma::accumulator, 16, 16, 8, float> acc[3][4];
#pragma unroll
    for (int i = 0; i < 3; i++)
#pragma unroll
        for (int j = 0; j < 4; j++) wmma::fill_fragment(acc[i][j], 0.f);

    for (int k0 = 0; k0 < 128; k0 += 32) {
#pragma unroll
        for (int h = 0; h < 6; h++) {
            int i4 = tid + h * 256;
            int r = i4 >> 3, c = (i4 & 7) * 4;
            float4 v = make_float4(0.f, 0.f, 0.f, 0.f);
            if (bm + r < M) {
                if constexpr (sizeof(AT) == 4) {
                    v = *(const float4*)((const float*)A + (long)(bm + r) * 128 + k0 + c);
                } else {
                    uint2 raw = *(const uint2*)((const __half*)A + (long)(bm + r) * 128 + k0 + c);
                    float2 a = __half22float2(*(__half2*)&raw.x);
                    float2 b = __half22float2(*(__half2*)&raw.y);
                    v = make_float4(a.x, a.y, b.x, b.y);
                }
            }
            As[r][c + 0] = wmma::__float_to_tf32(v.x);
            As[r][c + 1] = wmma::__float_to_tf32(v.y);
            As[r][c + 2] = wmma::__float_to_tf32(v.z);
            As[r][c + 3] = wmma::__float_to_tf32(v.w);
        }
#pragma unroll
        for (int h = 0; h < 4; h++) {
            int i4 = tid + h * 256;
            int r = i4 >> 5, c = (i4 & 31) * 4;
            float4 v = *(const float4*)(B + (long)(k0 + r) * 128 + c);
            Bs[r][c + 0] = wmma::__float_to_tf32(v.x);
            Bs[r][c + 1] = wmma::__float_to_tf32(v.y);
            Bs[r][c + 2] = wmma::__float_to_tf32(v.z);
            Bs[r][c + 3] = wmma::__float_to_tf32(v.w);
        }
        __syncthreads();
#pragma unroll
        for (int kk = 0; kk < 4; kk++) {
            wmma::fragment<wmma::matrix_a, 16, 16, 8, wmma::precision::tf32, wmma::row_major> af[3];
            wmma::fragment<wmma::matrix_b, 16, 16, 8, wmma::precision::tf32, wmma::row_major> bf[4];
#pragma unroll
            for (int i = 0; i < 3; i++)
                wmma::load_matrix_sync(af[i], &As[wm * 48 + i * 16][kk * 8], 36);
#pragma unroll
            for (int j = 0; j < 4; j++)
                wmma::load_matrix_sync(bf[j], &Bs[kk * 8][wn * 64 + j * 16], 136);
#pragma unroll
            for (int i = 0; i < 3; i++)
#pragma unroll
                for (int j = 0; j < 4; j++)
                    wmma::mma_sync(acc[i][j], af[i], bf[j], acc[i][j]);
        }
        __syncthreads();
    }
#pragma unroll
    for (int i = 0; i < 3; i++)
#pragma unroll
        for (int j = 0; j < 4; j++) {
            wmma::store_matrix_sync(&stage[wid][0][0], acc[i][j], 20, wmma::mem_row_major);
            __syncwarp();
            int r = bm + wm * 48 + i * 16 + (lane >> 1);
            float dsc = (r < M) ? dis[r] : 0.f;
            const float* srow = &stage[wid][lane >> 1][(lane & 1) * 8];
            __half2 h0 = __float22half2_rn(make_float2(srow[0] * dsc, srow[1] * dsc));
            __half2 h1 = __float22half2_rn(make_float2(srow[2] * dsc, srow[3] * dsc));
            __half2 h2 = __float22half2_rn(make_float2(srow[4] * dsc, srow[5] * dsc));
            __half2 h3 = __float22half2_rn(make_float2(srow[6] * dsc, srow[7] * dsc));
            uint4 pack;
            pack.x = *(unsigned*)&h0;
            pack.y = *(unsigned*)&h1;
            pack.z = *(unsigned*)&h2;
            pack.w = *(unsigned*)&h3;
            *(uint4*)(out + (long)r * 128 + wn * 64 + j * 16 + (lane & 1) * 8) = pack;
            __syncwarp();
        }
}

// ---------------- tf32 output GEMM: (x1+x2)[M,128] @ Wo[128,64] + bo ------
// A1, A2 in fp16.
__global__ __launch_bounds__(256) void gemm_out_tf32(
    const __half* __restrict__ A1, const __half* __restrict__ A2,
    const float* __restrict__ B, const float* __restrict__ bias,
    float* __restrict__ out, int M)
{
    __shared__ float As[128][36];
    __shared__ float Bs[32][72];
    __shared__ float Bt[16][72];
    int tid = threadIdx.x;
    int wid = tid >> 5;
    int bm = blockIdx.x * 128;

    for (int i = tid; i < 16 * 64; i += 256) Bt[i >> 6][i & 63] = bias[i & 63];
    __syncthreads();

    wmma::fragment<wmma::accumulator, 16, 16, 8, float> acc[4];
#pragma unroll
    for (int j = 0; j < 4; j++)
        wmma::load_matrix_sync(acc[j], &Bt[0][j * 16], 72, wmma::mem_row_major);

    for (int k0 = 0; k0 < 128; k0 += 32) {
#pragma unroll
        for (int h = 0; h < 4; h++) {
            int i4 = tid + h * 256;
            int r = i4 >> 3, c = (i4 & 7) * 4;
            float4 v = make_float4(0.f, 0.f, 0.f, 0.f);
            if (bm + r < M) {
                uint2 r1 = *(const uint2*)(A1 + (long)(bm + r) * 128 + k0 + c);
                uint2 r2 = *(const uint2*)(A2 + (long)(bm + r) * 128 + k0 + c);
                float2 a1 = __half22float2(*(__half2*)&r1.x);
                float2 b1 = __half22float2(*(__half2*)&r1.y);
                float2 a2 = __half22float2(*(__half2*)&r2.x);
                float2 b2 = __half22float2(*(__half2*)&r2.y);
                v.x = a1.x + a2.x; v.y = a1.y + a2.y;
                v.z = b1.x + b2.x; v.w = b1.y + b2.y;
            }
            As[r][c + 0] = wmma::__float_to_tf32(v.x);
            As[r][c + 1] = wmma::__float_to_tf32(v.y);
            As[r][c + 2] = wmma::__float_to_tf32(v.z);
            As[r][c + 3] = wmma::__float_to_tf32(v.w);
        }
        {
            int r = tid >> 4, c = (tid & 15) * 4;
            float4 v = *(const float4*)(B + (long)(k0 + r) * 64 + c);
            Bs[r][c + 0] = wmma::__float_to_tf32(v.x);
            Bs[r][c + 1] = wmma::__float_to_tf32(v.y);
            Bs[r][c + 2] = wmma::__float_to_tf32(v.z);
            Bs[r][c + 3] = wmma::__float_to_tf32(v.w);
            r = (tid + 256) >> 4; c = ((tid + 256) & 15) * 4;
            v = *(const float4*)(B + (long)(k0 + r) * 64 + c);
            Bs[r][c + 0] = wmma::__float_to_tf32(v.x);
            Bs[r][c + 1] = wmma::__float_to_tf32(v.y);
            Bs[r][c + 2] = wmma::__float_to_tf32(v.z);
            Bs[r][c + 3] = wmma::__float_to_tf32(v.w);
        }
        __syncthreads();
#pragma unroll
        for (int kk = 0; kk < 4; kk++) {
            wmma::fragment<wmma::matrix_a, 16, 16, 8, wmma::precision::tf32, wmma::row_major> af;
            wmma::fragment<wmma::matrix_b, 16, 16, 8, wmma::precision::tf32, wmma::row_major> bf[4];
            wmma::load_matrix_sync(af, &As[wid * 16][kk * 8], 36);
#pragma unroll
            for (int j = 0; j < 4; j++)
                wmma::load_matrix_sync(bf[j], &Bs[kk * 8][j * 16], 72);
#pragma unroll
            for (int j = 0; j < 4; j++)
                wmma::mma_sync(acc[j], af, bf[j], acc[j]);
        }
        __syncthreads();
    }
    int r = bm + wid * 16;
    if (r + 16 <= M) {
#pragma unroll
        for (int j = 0; j < 4; j++)
            wmma::store_matrix_sync(out + (long)r * 64 + j * 16,
                                    acc[j], 64, wmma::mem_row_major);
    }
}

// ---------------- aggregation (R7): warp/node, 8-wide, plain sum ----------
// Output now fp16.
__device__ __forceinline__ float4 gather_h(const __half* hs, int s, int lane) {
    uint2 raw = *(const uint2*)(hs + (long)s * 128 + lane * 4);
    float2 a = __half22float2(*(__half2*)&raw.x);
    float2 b = __half22float2(*(__half2*)&raw.y);
    return make_float4(a.x, a.y, b.x, b.y);
}

__global__ __launch_bounds__(256) void aggregate_s(
    const __half* __restrict__ hs, const float* __restrict__ bias,
    __half* __restrict__ xo)
{
    int gw = (blockIdx.x * blockDim.x + threadIdx.x) >> 5;
    int lane = threadIdx.x & 31;
    if (gw >= N_NODES) return;
    int beg = g_row[gw];
    int end = g_row[gw + 1];
    float4 acc = gather_h(hs, gw, lane);   // self term, pre-scaled
    int e = beg;
    for (; e + 8 <= end; e += 8) {
        int s0 = g_csr[e],     s1 = g_csr[e + 1], s2 = g_csr[e + 2], s3 = g_csr[e + 3];
        int s4 = g_csr[e + 4], s5 = g_csr[e + 5], s6 = g_csr[e + 6], s7 = g_csr[e + 7];
        float4 v0 = gather_h(hs, s0, lane);
        float4 v1 = gather_h(hs, s1, lane);
        float4 v2 = gather_h(hs, s2, lane);
        float4 v3 = gather_h(hs, s3, lane);
        float4 v4 = gather_h(hs, s4, lane);
        float4 v5 = gather_h(hs, s5, lane);
        float4 v6 = gather_h(hs, s6, lane);
        float4 v7 = gather_h(hs, s7, lane);
        acc.x += (v0.x + v1.x) + (v2.x + v3.x) + (v4.x + v5.x) + (v6.x + v7.x);
        acc.y += (v0.y + v1.y) + (v2.y + v3.y) + (v4.y + v5.y) + (v6.y + v7.y);
        acc.z += (v0.z + v1.z) + (v2.z + v3.z) + (v4.z + v5.z) + (v6.z + v7.z);
        acc.w += (v0.w + v1.w) + (v2.w + v3.w) + (v4.w + v5.w) + (v6.w + v7.w);
    }
    for (; e < end; e++) {
        float4 v = gather_h(hs, g_csr[e], lane);
        acc.x += v.x; acc.y += v.y; acc.z += v.z; acc.w += v.w;
    }
    float dd = g_dis[gw];
    float4 b = *(const float4*)(bias + lane * 4);
    __half2 o0 = __float22half2_rn(make_float2(
        fmaxf(acc.x * dd + b.x, 0.f), fmaxf(acc.y * dd + b.y, 0.f)));
    __half2 o1 = __float22half2_rn(make_float2(
        fmaxf(acc.z * dd + b.z, 0.f), fmaxf(acc.w * dd + b.w, 0.f)));
    uint2 pack;
    pack.x = *(unsigned*)&o0;
    pack.y = *(unsigned*)&o1;
    *(uint2*)(xo + (long)gw * 128 + lane * 4) = pack;
}

// ---------------- launch ---------------------------------------------------
extern "C" void kernel_launch(void* const* d_in, const int* in_sizes, int n_in,
                              void* d_out, int out_size)
{
    const float* x  = (const float*)d_in[0];
    const void*  ei = d_in[1];
    const float* W1 = (const float*)d_in[2];
    const float* b1 = (const float*)d_in[3];
    const float* W2 = (const float*)d_in[4];
    const float* b2 = (const float*)d_in[5];
    const float* Wo = (const float*)d_in[6];
    const float* bo = (const float*)d_in[7];
    float* out = (float*)d_out;

    __half *hs, *x1, *x2;
    float* dis;
    cudaGetSymbolAddress((void**)&hs,  g_hs);
    cudaGetSymbolAddress((void**)&x1,  g_x1);
    cudaGetSymbolAddress((void**)&x2,  g_x2);
    cudaGetSymbolAddress((void**)&dis, g_dis);

    const int M = N_NODES;
    int gB  = (M + 191) / 192;
    int gBo = (M + 127) / 128;
    int gN  = (M + 255) / 256;
    int gE8 = (N_EDGES + 2047) / 2048;
    int gAg = (M * 32 + 255) / 256;

    k_init<<<gN, 256>>>(ei);
    k_hist<<<gE8, 256>>>(ei);
    k_scan1<<<SCAN_NB, SCAN_T>>>();
    k_scan2<<<1, 256>>>();
    k_scan3<<<SCAN_NB, SCAN_T>>>();
    k_fill<<<gE8, 256>>>(ei);

    gemm_tf32<float><<<gB, 256>>>(x, W1, hs, dis, M);
    aggregate_s<<<gAg, 256>>>(hs, b1, x1);
    gemm_tf32<__half><<<gB, 256>>>(x1, W2, hs, dis, M);
    aggregate_s<<<gAg, 256>>>(hs, b2, x2);
    gemm_out_tf32<<<gBo, 256>>>(x1, x2, Wo, bo, out, M);
}